// round 3
// baseline (speedup 1.0000x reference)
#include <cuda_runtime.h>

#define N_NODES 50000
#define N_EDGES 800000
#define IN_C 64
#define HID_C 128
#define OUT_C 64

// ---------------- scratch (static device globals; no allocation) ----------------
__device__ float g_Sx[N_NODES * IN_C];    // sum of x[src] per dst  (layer 1)
__device__ float g_S2[N_NODES * HID_C];   // sum of h[src] per dst  (layer 2)
__device__ float g_h [N_NODES * HID_C];   // hidden activations
__device__ float g_deg[N_NODES];          // in-degree (float, exact for small counts)
__device__ float g_se [N_NODES];          // sum of edge_attr per dst
__device__ int   g_any;                   // != 0 -> edge_index is int32

// ---------------- zero scratch ----------------
__global__ void zero_kernel() {
    int i = blockIdx.x * blockDim.x + threadIdx.x;
    int stride = gridDim.x * blockDim.x;
    for (int k = i; k < N_NODES * IN_C;  k += stride) g_Sx[k] = 0.f;
    for (int k = i; k < N_NODES * HID_C; k += stride) g_S2[k] = 0.f;
    for (int k = i; k < N_NODES; k += stride) { g_deg[k] = 0.f; g_se[k] = 0.f; }
    if (i == 0) g_any = 0;
}

// ---------------- detect int32 vs int64 edge_index ----------------
// Values are node ids < 2^31, so int64 storage has every odd 32-bit word == 0.
__global__ void detect_kernel(const int* __restrict__ ei32) {
    int v = 0;
    for (int k = threadIdx.x; k < 1024; k += blockDim.x) v |= ei32[2 * k + 1];
    if (v) atomicOr(&g_any, 1);
}

__device__ __forceinline__ void load_edge(const void* ei, int e, bool is64,
                                          long long& src, long long& dst) {
    if (is64) {
        const long long* p = (const long long*)ei;
        src = __ldg(p + e); dst = __ldg(p + N_EDGES + e);
    } else {
        const int* p = (const int*)ei;
        src = __ldg(p + e); dst = __ldg(p + N_EDGES + e);
    }
}

// ---------------- layer-1 scatter: 16 threads per edge (64 ch as 4x float4) ----
__global__ __launch_bounds__(256) void scatter1_kernel(
    const float* __restrict__ x, const void* __restrict__ ei,
    const float* __restrict__ ea) {
    int tid = blockIdx.x * blockDim.x + threadIdx.x;
    int e = tid >> 4;
    int c = tid & 15;
    if (e >= N_EDGES) return;
    bool is64 = (g_any == 0);
    long long src, dst;
    load_edge(ei, e, is64, src, dst);
    float4 v = __ldg(((const float4*)x) + src * (IN_C / 4) + c);
    atomicAdd(&((float4*)g_Sx)[dst * (IN_C / 4) + c], v);
    if (c == 0) {
        atomicAdd(&g_se[dst], __ldg(ea + e));
        atomicAdd(&g_deg[dst], 1.0f);
    }
}

// ---------------- layer-2 scatter: warp per edge (128 ch as 32x float4) -------
__global__ __launch_bounds__(256) void scatter2_kernel(const void* __restrict__ ei) {
    int tid = blockIdx.x * blockDim.x + threadIdx.x;
    int e = tid >> 5;
    int l = tid & 31;
    if (e >= N_EDGES) return;
    bool is64 = (g_any == 0);
    long long src, dst;
    load_edge(ei, e, is64, src, dst);
    float4 v = ((const float4*)g_h)[src * (HID_C / 4) + l];
    atomicAdd(&((float4*)g_S2)[dst * (HID_C / 4) + l], v);
}

// ---------------- dense layer 1: h = relu((deg+1)(x@Wi + b) + (S+x)@Wj + se*We)
// W1: [129, 128] row-major. rows 0..63 = Wi, 64..127 = Wj, 128 = We.
__global__ __launch_bounds__(128) void dense1_kernel(
    const float* __restrict__ x, const float* __restrict__ W1,
    const float* __restrict__ b1) {
    extern __shared__ float sm[];
    float* Ws = sm;                          // 129*128
    float* xs = Ws + 129 * HID_C;            // 64
    float* ss = xs + IN_C;                   // 64
    float* bs = ss + IN_C;                   // 128
    int tid = threadIdx.x;
    for (int i = tid; i < 129 * HID_C; i += 128) Ws[i] = W1[i];
    bs[tid] = b1[tid];
    __syncthreads();

    for (int n = blockIdx.x; n < N_NODES; n += gridDim.x) {
        if (tid < IN_C) xs[tid] = x[n * IN_C + tid];
        else            ss[tid - IN_C] = g_Sx[n * IN_C + (tid - IN_C)];
        __syncthreads();
        float degp1 = g_deg[n] + 1.0f;
        float sev   = g_se[n];
        float d1 = bs[tid];
        float d2 = 0.f;
#pragma unroll
        for (int k = 0; k < IN_C; k++) {
            float xv = xs[k];
            d1 = fmaf(xv,           Ws[k * HID_C + tid],            d1);
            d2 = fmaf(ss[k] + xv,   Ws[(IN_C + k) * HID_C + tid],   d2);
        }
        float v = fmaf(degp1, d1, d2) + sev * Ws[2 * IN_C * HID_C + tid];
        g_h[n * HID_C + tid] = fmaxf(v, 0.f);
        __syncthreads();
    }
}

// ---------------- dense layer 2: out = relu(...), 2 nodes per block-iter -----
// W2: [257, 64]. rows 0..127 = Wi, 128..255 = Wj, 256 = We.
__global__ __launch_bounds__(128) void dense2_kernel(
    const float* __restrict__ W2, const float* __restrict__ b2,
    float* __restrict__ out) {
    extern __shared__ float sm[];
    float* Ws  = sm;                          // 257*64
    float* hs  = Ws + 257 * OUT_C;            // 2*128
    float* s2s = hs + 2 * HID_C;              // 2*128
    float* bs  = s2s + 2 * HID_C;             // 64
    int tid = threadIdx.x;
    int sub = tid >> 6;       // node sub-index 0/1
    int j   = tid & 63;       // output column
    for (int i = tid; i < 257 * OUT_C; i += 128) Ws[i] = W2[i];
    if (tid < OUT_C) bs[tid] = b2[tid];
    __syncthreads();

    for (int n0 = blockIdx.x * 2; n0 < N_NODES; n0 += gridDim.x * 2) {
        for (int i = tid; i < 2 * HID_C; i += 128) {
            int gi = n0 * HID_C + i;
            bool ok = gi < N_NODES * HID_C;
            hs[i]  = ok ? g_h[gi]  : 0.f;
            s2s[i] = ok ? g_S2[gi] : 0.f;
        }
        __syncthreads();
        int n = n0 + sub;
        if (n < N_NODES) {
            float degp1 = g_deg[n] + 1.0f;
            float sev   = g_se[n];
            const float* hp = hs  + sub * HID_C;
            const float* sp = s2s + sub * HID_C;
            float d1 = bs[j];
            float d2 = 0.f;
#pragma unroll 8
            for (int k = 0; k < HID_C; k++) {
                float hv = hp[k];
                d1 = fmaf(hv,           Ws[k * OUT_C + j],             d1);
                d2 = fmaf(sp[k] + hv,   Ws[(HID_C + k) * OUT_C + j],   d2);
            }
            float v = fmaf(degp1, d1, d2) + sev * Ws[2 * HID_C * OUT_C + j];
            out[n * OUT_C + j] = fmaxf(v, 0.f);
        }
        __syncthreads();
    }
}

// ---------------- log_softmax over 64 columns, warp per row -------------------
__global__ __launch_bounds__(256) void lsm_kernel(float* __restrict__ out) {
    int tid = blockIdx.x * blockDim.x + threadIdx.x;
    int w = tid >> 5;
    int l = tid & 31;
    if (w >= N_NODES) return;
    float* row = out + (long long)w * OUT_C;
    float a = row[l], b = row[l + 32];
    float m = fmaxf(a, b);
#pragma unroll
    for (int o = 16; o; o >>= 1) m = fmaxf(m, __shfl_xor_sync(0xffffffffu, m, o));
    float s = expf(a - m) + expf(b - m);
#pragma unroll
    for (int o = 16; o; o >>= 1) s += __shfl_xor_sync(0xffffffffu, s, o);
    float ls = logf(s) + m;
    row[l] = a - ls;
    row[l + 32] = b - ls;
}

// ---------------- launch ------------------------------------------------------
extern "C" void kernel_launch(void* const* d_in, const int* in_sizes, int n_in,
                              void* d_out, int out_size) {
    const float* x  = (const float*)d_in[0];
    const void*  ei = d_in[1];                 // int64 or int32, detected on device
    const float* ea = (const float*)d_in[2];
    const float* W1 = (const float*)d_in[3];
    const float* b1 = (const float*)d_in[4];
    const float* W2 = (const float*)d_in[5];
    const float* b2 = (const float*)d_in[6];
    float* out = (float*)d_out;

    // Not stream ops: legal during capture, idempotent, called every time
    // (no static guards — kernel_launch does identical work on every call).
    int smem1 = (129 * HID_C + 2 * IN_C + HID_C) * 4;
    int smem2 = (257 * OUT_C + 4 * HID_C + OUT_C) * 4;
    cudaFuncSetAttribute(dense1_kernel, cudaFuncAttributeMaxDynamicSharedMemorySize, smem1);
    cudaFuncSetAttribute(dense2_kernel, cudaFuncAttributeMaxDynamicSharedMemorySize, smem2);

    zero_kernel<<<4096, 256>>>();
    detect_kernel<<<1, 256>>>((const int*)ei);
    scatter1_kernel<<<(N_EDGES * 16 + 255) / 256, 256>>>(x, ei, ea);
    dense1_kernel<<<444, 128, smem1>>>(x, W1, b1);
    scatter2_kernel<<<(N_EDGES * 32 + 255) / 256, 256>>>(ei);
    dense2_kernel<<<740, 128, smem2>>>(W2, b2, out);
    lsm_kernel<<<(N_NODES * 32 + 255) / 256, 256>>>(out);
}

// round 4
// speedup vs baseline: 1.6408x; 1.6408x over previous
#include <cuda_runtime.h>

#define N_NODES 50000
#define N_EDGES 800000
#define IN_C 64
#define HID_C 128
#define OUT_C 64

// ---------------- scratch (static device globals; no allocation) ----------------
__device__ float g_Sx[N_NODES * IN_C];    // sum of x[src] per dst  (layer 1)
__device__ float g_S2[N_NODES * HID_C];   // sum of h[src] per dst  (layer 2)
__device__ float g_h [N_NODES * HID_C];   // hidden activations
__device__ float g_deg[N_NODES];          // in-degree
__device__ float g_se [N_NODES];          // sum of edge_attr per dst
__device__ int   g_any;                   // != 0 -> edge_index is int32

// ---------------- f32x2 packed helpers (B300 FFMA2 path) ----------------
__device__ __forceinline__ void ffma2(unsigned long long& acc,
                                      unsigned long long a, unsigned long long b) {
    asm("fma.rn.f32x2 %0, %1, %2, %0;" : "+l"(acc) : "l"(a), "l"(b));
}
__device__ __forceinline__ unsigned long long f2ull(float a, float b) {
    unsigned long long u;
    asm("mov.b64 %0, {%1, %2};" : "=l"(u) : "f"(a), "f"(b));
    return u;
}
__device__ __forceinline__ float2 ull2f2(unsigned long long u) {
    float2 f;
    asm("mov.b64 {%0, %1}, %2;" : "=f"(f.x), "=f"(f.y) : "l"(u));
    return f;
}

// ---------------- zero scratch ----------------
__global__ void zero_kernel() {
    int i = blockIdx.x * blockDim.x + threadIdx.x;
    int stride = gridDim.x * blockDim.x;
    for (int k = i; k < N_NODES * IN_C;  k += stride) g_Sx[k] = 0.f;
    for (int k = i; k < N_NODES * HID_C; k += stride) g_S2[k] = 0.f;
    for (int k = i; k < N_NODES; k += stride) { g_deg[k] = 0.f; g_se[k] = 0.f; }
    if (i == 0) g_any = 0;
}

// ---------------- detect int32 vs int64 edge_index ----------------
__global__ void detect_kernel(const int* __restrict__ ei32) {
    int v = 0;
    for (int k = threadIdx.x; k < 1024; k += blockDim.x) v |= ei32[2 * k + 1];
    if (v) atomicOr(&g_any, 1);
}

__device__ __forceinline__ void load_edge(const void* ei, int e, bool is64,
                                          long long& src, long long& dst) {
    if (is64) {
        const long long* p = (const long long*)ei;
        src = __ldg(p + e); dst = __ldg(p + N_EDGES + e);
    } else {
        const int* p = (const int*)ei;
        src = __ldg(p + e); dst = __ldg(p + N_EDGES + e);
    }
}

// ---------------- layer-1 scatter: 16 threads per edge ----------------
__global__ __launch_bounds__(256) void scatter1_kernel(
    const float* __restrict__ x, const void* __restrict__ ei,
    const float* __restrict__ ea) {
    int tid = blockIdx.x * blockDim.x + threadIdx.x;
    int e = tid >> 4;
    int c = tid & 15;
    if (e >= N_EDGES) return;
    bool is64 = (g_any == 0);
    long long src, dst;
    load_edge(ei, e, is64, src, dst);
    float4 v = __ldg(((const float4*)x) + src * (IN_C / 4) + c);
    atomicAdd(&((float4*)g_Sx)[dst * (IN_C / 4) + c], v);
    if (c == 0) {
        atomicAdd(&g_se[dst], __ldg(ea + e));
        atomicAdd(&g_deg[dst], 1.0f);
    }
}

// ---------------- layer-2 scatter: warp per edge ----------------
__global__ __launch_bounds__(256) void scatter2_kernel(const void* __restrict__ ei) {
    int tid = blockIdx.x * blockDim.x + threadIdx.x;
    int e = tid >> 5;
    int l = tid & 31;
    if (e >= N_EDGES) return;
    bool is64 = (g_any == 0);
    long long src, dst;
    load_edge(ei, e, is64, src, dst);
    float4 v = ((const float4*)g_h)[src * (HID_C / 4) + l];
    atomicAdd(&((float4*)g_S2)[dst * (HID_C / 4) + l], v);
}

// ==================== dense layer 1 ====================
// h = relu( v @ W1 + degp1*b1 ), v = [degp1*x (64), Sx+x (64), se (1)]
// Register-blocked: 8 warps x 4 nodes, thread owns 4 out cols, FFMA2 math.
#define D1_N 32
__global__ __launch_bounds__(256) void dense1_kernel(
    const float* __restrict__ x, const float* __restrict__ W1,
    const float* __restrict__ b1) {
    extern __shared__ float sm[];
    float* Ws = sm;                      // 129*128 = 16512
    float* bs = Ws + 16512;              // 128
    float* dg = bs + 128;                // 32
    float* sep = dg + 32;                // 32 (pad/unused slots ok)
    unsigned long long* vsd = (unsigned long long*)(sep + 32); // 32 rows x 130 ull
    int tid = threadIdx.x;
    int warp = tid >> 5, lane = tid & 31;
    int c4 = lane * 4;
    for (int i = tid; i < 16512; i += 256) Ws[i] = W1[i];
    if (tid < 128) bs[tid] = b1[tid];

    int iters = (N_NODES + D1_N - 1) / D1_N;
    for (int it = blockIdx.x; it < iters; it += gridDim.x) {
        int base = it * D1_N;
        __syncthreads();                 // protect vsd reuse (and Ws on first pass)
        if (tid < D1_N) {
            int gn = base + tid;
            bool ok = gn < N_NODES;
            dg[tid] = ok ? g_deg[gn] + 1.0f : 1.0f;
            float s = ok ? g_se[gn] : 0.0f;
            vsd[tid * 130 + 128] = f2ull(s, s);
        }
        __syncthreads();
        for (int idx = tid; idx < D1_N * 64; idx += 256) {
            int n = idx >> 6, k = idx & 63;
            int gn = base + n;
            float xv = 0.f, sv = 0.f;
            if (gn < N_NODES) { xv = x[gn * 64 + k]; sv = g_Sx[gn * 64 + k]; }
            float a = dg[n] * xv;
            float b = sv + xv;
            vsd[n * 130 + k]      = f2ull(a, a);
            vsd[n * 130 + 64 + k] = f2ull(b, b);
        }
        __syncthreads();

        unsigned long long a0[4], a1[4];
#pragma unroll
        for (int i = 0; i < 4; i++) { a0[i] = 0ull; a1[i] = 0ull; }
        const float* wp = Ws + c4;
        const unsigned long long* v0 = vsd + (warp * 4) * 130;
        for (int k2 = 0; k2 < 64; k2++) {
            ulonglong2 wa = *(const ulonglong2*)(wp + (2 * k2) * 128);
            ulonglong2 wb = *(const ulonglong2*)(wp + (2 * k2 + 1) * 128);
#pragma unroll
            for (int i = 0; i < 4; i++) {
                ulonglong2 vv = *(const ulonglong2*)(v0 + i * 130 + 2 * k2);
                ffma2(a0[i], wa.x, vv.x); ffma2(a1[i], wa.y, vv.x);
                ffma2(a0[i], wb.x, vv.y); ffma2(a1[i], wb.y, vv.y);
            }
        }
        {   // k = 128 (edge-attr row)
            ulonglong2 wt = *(const ulonglong2*)(wp + 128 * 128);
#pragma unroll
            for (int i = 0; i < 4; i++) {
                unsigned long long vt = v0[i * 130 + 128];
                ffma2(a0[i], wt.x, vt); ffma2(a1[i], wt.y, vt);
            }
        }
#pragma unroll
        for (int i = 0; i < 4; i++) {
            int ln = warp * 4 + i;
            int gn = base + ln;
            if (gn < N_NODES) {
                float d = dg[ln];
                float2 lo = ull2f2(a0[i]), hi = ull2f2(a1[i]);
                float4 r;
                r.x = fmaxf(fmaf(d, bs[c4 + 0], lo.x), 0.f);
                r.y = fmaxf(fmaf(d, bs[c4 + 1], lo.y), 0.f);
                r.z = fmaxf(fmaf(d, bs[c4 + 2], hi.x), 0.f);
                r.w = fmaxf(fmaf(d, bs[c4 + 3], hi.y), 0.f);
                *(float4*)&g_h[gn * 128 + c4] = r;
            }
        }
    }
}

// ==================== dense layer 2 (+ fused relu & log_softmax) ====================
// out = log_softmax( relu( v @ W2 + degp1*b2 ) ), v = [degp1*h (128), S2+h (128), se]
// 8 warps x 8 nodes, thread owns 2 out cols (FFMA2), warp-shfl log_softmax epilogue.
#define D2_N 64
__global__ __launch_bounds__(256) void dense2_kernel(
    const float* __restrict__ W2, const float* __restrict__ b2,
    float* __restrict__ out) {
    extern __shared__ float sm[];
    float* Ws = sm;                      // 257*64 = 16448
    float* bs = Ws + 16448;              // 64
    float* dg = bs + 64;                 // 64
    unsigned long long* vsd = (unsigned long long*)(dg + 64); // 64 rows x 258 ull
    int tid = threadIdx.x;
    int warp = tid >> 5, lane = tid & 31;
    int j2 = lane * 2;
    for (int i = tid; i < 16448; i += 256) Ws[i] = W2[i];
    if (tid < 64) bs[tid] = b2[tid];

    int iters = (N_NODES + D2_N - 1) / D2_N;
    for (int it = blockIdx.x; it < iters; it += gridDim.x) {
        int base = it * D2_N;
        __syncthreads();
        if (tid < D2_N) {
            int gn = base + tid;
            bool ok = gn < N_NODES;
            dg[tid] = ok ? g_deg[gn] + 1.0f : 1.0f;
            float s = ok ? g_se[gn] : 0.0f;
            vsd[tid * 258 + 256] = f2ull(s, s);
        }
        __syncthreads();
        for (int idx = tid; idx < D2_N * 128; idx += 256) {
            int n = idx >> 7, k = idx & 127;
            int gn = base + n;
            float hv = 0.f, sv = 0.f;
            if (gn < N_NODES) { hv = g_h[gn * 128 + k]; sv = g_S2[gn * 128 + k]; }
            float a = dg[n] * hv;
            float b = sv + hv;
            vsd[n * 258 + k]       = f2ull(a, a);
            vsd[n * 258 + 128 + k] = f2ull(b, b);
        }
        __syncthreads();

        unsigned long long acc[8];
#pragma unroll
        for (int i = 0; i < 8; i++) acc[i] = 0ull;
        const float* wp = Ws + j2;
        const unsigned long long* v0 = vsd + (warp * 8) * 258;
        for (int k4 = 0; k4 < 64; k4++) {
            int k = k4 * 4;
            unsigned long long w0 = *(const unsigned long long*)(wp + (k + 0) * 64);
            unsigned long long w1 = *(const unsigned long long*)(wp + (k + 1) * 64);
            unsigned long long w2 = *(const unsigned long long*)(wp + (k + 2) * 64);
            unsigned long long w3 = *(const unsigned long long*)(wp + (k + 3) * 64);
#pragma unroll
            for (int i = 0; i < 8; i++) {
                ulonglong2 va = *(const ulonglong2*)(v0 + i * 258 + k);
                ulonglong2 vb = *(const ulonglong2*)(v0 + i * 258 + k + 2);
                ffma2(acc[i], w0, va.x);
                ffma2(acc[i], w1, va.y);
                ffma2(acc[i], w2, vb.x);
                ffma2(acc[i], w3, vb.y);
            }
        }
        {   // k = 256 (edge-attr row)
            unsigned long long wt = *(const unsigned long long*)(wp + 256 * 64);
#pragma unroll
            for (int i = 0; i < 8; i++) ffma2(acc[i], wt, v0[i * 258 + 256]);
        }

        float bx = bs[j2], by = bs[j2 + 1];
#pragma unroll
        for (int i = 0; i < 8; i++) {
            int ln = warp * 8 + i;
            int gn = base + ln;
            float d = dg[ln];
            float2 a = ull2f2(acc[i]);
            float rx = fmaxf(fmaf(d, bx, a.x), 0.f);
            float ry = fmaxf(fmaf(d, by, a.y), 0.f);
            float m = fmaxf(rx, ry);
#pragma unroll
            for (int o = 16; o; o >>= 1) m = fmaxf(m, __shfl_xor_sync(0xffffffffu, m, o));
            float s = __expf(rx - m) + __expf(ry - m);
#pragma unroll
            for (int o = 16; o; o >>= 1) s += __shfl_xor_sync(0xffffffffu, s, o);
            float ls = __logf(s) + m;
            if (gn < N_NODES) {
                float2 r = make_float2(rx - ls, ry - ls);
                *(float2*)&out[gn * 64 + j2] = r;
            }
        }
    }
}

// ---------------- launch ------------------------------------------------------
extern "C" void kernel_launch(void* const* d_in, const int* in_sizes, int n_in,
                              void* d_out, int out_size) {
    const float* x  = (const float*)d_in[0];
    const void*  ei = d_in[1];
    const float* ea = (const float*)d_in[2];
    const float* W1 = (const float*)d_in[3];
    const float* b1 = (const float*)d_in[4];
    const float* W2 = (const float*)d_in[5];
    const float* b2 = (const float*)d_in[6];
    float* out = (float*)d_out;

    // smem sizes (bytes)
    int smem1 = (16512 + 128 + 32 + 32) * 4 + 32 * 130 * 8;   // 100,096 B
    int smem2 = (16448 + 64 + 64) * 4 + 64 * 258 * 8;         // 198,400 B
    cudaFuncSetAttribute(dense1_kernel, cudaFuncAttributeMaxDynamicSharedMemorySize, smem1);
    cudaFuncSetAttribute(dense2_kernel, cudaFuncAttributeMaxDynamicSharedMemorySize, smem2);

    zero_kernel<<<4096, 256>>>();
    detect_kernel<<<1, 256>>>((const int*)ei);
    scatter1_kernel<<<(N_EDGES * 16 + 255) / 256, 256>>>(x, ei, ea);
    dense1_kernel<<<296, 256, smem1>>>(x, W1, b1);
    scatter2_kernel<<<(N_EDGES * 32 + 255) / 256, 256>>>(ei);
    dense2_kernel<<<148, 256, smem2>>>(W2, b2, out);
}

// round 5
// speedup vs baseline: 2.1605x; 1.3168x over previous
#include <cuda_runtime.h>

#define N_NODES 50000
#define N_EDGES 800000
#define IN_C 64
#define HID_C 128
#define OUT_C 64
#define SCAN_BLOCKS 196   // 196*256 = 50176 >= N_NODES

// ---------------- scratch (static device globals; no allocation) ----------------
__device__ float g_Sx[N_NODES * IN_C];    // sum_{src->d} x[src]
__device__ float g_S2[N_NODES * HID_C];   // sum_{src->d} h[src]
__device__ float g_h [N_NODES * HID_C];   // hidden activations
__device__ float g_deg[N_NODES];          // in-degree
__device__ float g_se [N_NODES];          // sum of edge_attr per dst
__device__ int   g_cnt[N_NODES];          // histogram counts
__device__ int   g_rp [N_NODES];          // CSR row pointer (exclusive scan)
__device__ int   g_cur[N_NODES];          // fill cursors
__device__ int   g_bs [256];              // block sums for 2-level scan
__device__ int   g_srcs[N_EDGES];         // CSR column (src) indices
__device__ int   g_any;                   // != 0 -> edge_index is int32

// ---------------- f32x2 packed helpers (B300 FFMA2 path) ----------------
__device__ __forceinline__ void ffma2(unsigned long long& acc,
                                      unsigned long long a, unsigned long long b) {
    asm("fma.rn.f32x2 %0, %1, %2, %0;" : "+l"(acc) : "l"(a), "l"(b));
}
__device__ __forceinline__ unsigned long long f2ull(float a, float b) {
    unsigned long long u;
    asm("mov.b64 %0, {%1, %2};" : "=l"(u) : "f"(a), "f"(b));
    return u;
}
__device__ __forceinline__ float2 ull2f2(unsigned long long u) {
    float2 f;
    asm("mov.b64 {%0, %1}, %2;" : "=f"(f.x), "=f"(f.y) : "l"(u));
    return f;
}

// ---------------- zero small scratch ----------------
__global__ void zero_kernel() {
    int i = blockIdx.x * blockDim.x + threadIdx.x;
    int stride = gridDim.x * blockDim.x;
    for (int k = i; k < N_NODES; k += stride) { g_cnt[k] = 0; g_se[k] = 0.f; }
    if (i == 0) g_any = 0;
}

// ---------------- detect int32 vs int64 edge_index ----------------
__global__ void detect_kernel(const int* __restrict__ ei32) {
    int v = 0;
    for (int k = threadIdx.x; k < 1024; k += blockDim.x) v |= ei32[2 * k + 1];
    if (v) atomicOr(&g_any, 1);
}

__device__ __forceinline__ void load_edge(const void* ei, int e, bool is64,
                                          int& src, int& dst) {
    if (is64) {
        const long long* p = (const long long*)ei;
        src = (int)__ldg(p + e); dst = (int)__ldg(p + N_EDGES + e);
    } else {
        const int* p = (const int*)ei;
        src = __ldg(p + e); dst = __ldg(p + N_EDGES + e);
    }
}

// ---------------- CSR build ----------------
__global__ __launch_bounds__(256) void hist_kernel(const void* __restrict__ ei,
                                                   const float* __restrict__ ea) {
    int e = blockIdx.x * blockDim.x + threadIdx.x;
    if (e >= N_EDGES) return;
    bool is64 = (g_any == 0);
    int src, dst;
    load_edge(ei, e, is64, src, dst);
    atomicAdd(&g_cnt[dst], 1);
    atomicAdd(&g_se[dst], __ldg(ea + e));
}

// block-local exclusive scan of g_cnt -> g_rp, block totals -> g_bs
__global__ __launch_bounds__(256) void scan1_kernel() {
    __shared__ int s[256];
    int t = threadIdx.x;
    int i = blockIdx.x * 256 + t;
    int c = (i < N_NODES) ? g_cnt[i] : 0;
    s[t] = c;
    __syncthreads();
    for (int o = 1; o < 256; o <<= 1) {
        int v = (t >= o) ? s[t - o] : 0;
        __syncthreads();
        s[t] += v;
        __syncthreads();
    }
    if (i < N_NODES) g_rp[i] = s[t] - c;
    if (t == 255) g_bs[blockIdx.x] = s[255];
}

// exclusive scan of g_bs in one block
__global__ __launch_bounds__(256) void scan2_kernel() {
    __shared__ int s[256];
    int t = threadIdx.x;
    int c = (t < SCAN_BLOCKS) ? g_bs[t] : 0;
    s[t] = c;
    __syncthreads();
    for (int o = 1; o < 256; o <<= 1) {
        int v = (t >= o) ? s[t - o] : 0;
        __syncthreads();
        s[t] += v;
        __syncthreads();
    }
    if (t < SCAN_BLOCKS) g_bs[t] = s[t] - c;
}

// add block offsets; init cursors; materialize deg as float
__global__ __launch_bounds__(256) void scan3_kernel() {
    int i = blockIdx.x * 256 + threadIdx.x;
    if (i >= N_NODES) return;
    int rp = g_rp[i] + g_bs[i >> 8];
    g_rp[i] = rp;
    g_cur[i] = rp;
    g_deg[i] = (float)g_cnt[i];
}

__global__ __launch_bounds__(256) void fill_kernel(const void* __restrict__ ei) {
    int e = blockIdx.x * blockDim.x + threadIdx.x;
    if (e >= N_EDGES) return;
    bool is64 = (g_any == 0);
    int src, dst;
    load_edge(ei, e, is64, src, dst);
    int p = atomicAdd(&g_cur[dst], 1);
    g_srcs[p] = src;
}

// ---------------- pull layer 1: 16 threads per dst, 64 ch as float4 ----------
__global__ __launch_bounds__(256) void pull1_kernel(const float* __restrict__ x) {
    int tid = blockIdx.x * blockDim.x + threadIdx.x;
    int d = tid >> 4, c = tid & 15;
    if (d >= N_NODES) return;
    int beg = g_rp[d];
    int end = beg + g_cnt[d];
    float4 acc = make_float4(0.f, 0.f, 0.f, 0.f);
#pragma unroll 4
    for (int j = beg; j < end; j++) {
        int s = __ldg(&g_srcs[j]);
        float4 v = __ldg((const float4*)x + s * (IN_C / 4) + c);
        acc.x += v.x; acc.y += v.y; acc.z += v.z; acc.w += v.w;
    }
    ((float4*)g_Sx)[d * (IN_C / 4) + c] = acc;
}

// ---------------- pull layer 2: warp per dst, 128 ch as float4 ---------------
__global__ __launch_bounds__(256) void pull2_kernel() {
    int tid = blockIdx.x * blockDim.x + threadIdx.x;
    int d = tid >> 5, c = tid & 31;
    if (d >= N_NODES) return;
    int beg = g_rp[d];
    int end = beg + g_cnt[d];
    float4 acc = make_float4(0.f, 0.f, 0.f, 0.f);
#pragma unroll 4
    for (int j = beg; j < end; j++) {
        int s = __ldg(&g_srcs[j]);
        float4 v = __ldg((const float4*)g_h + s * (HID_C / 4) + c);
        acc.x += v.x; acc.y += v.y; acc.z += v.z; acc.w += v.w;
    }
    ((float4*)g_S2)[d * (HID_C / 4) + c] = acc;
}

// ==================== dense layer 1 (unchanged from R4) ====================
// h = relu( v @ W1 + degp1*b1 ), v = [degp1*x (64), Sx+x (64), se (1)]
#define D1_N 32
__global__ __launch_bounds__(256) void dense1_kernel(
    const float* __restrict__ x, const float* __restrict__ W1,
    const float* __restrict__ b1) {
    extern __shared__ float sm[];
    float* Ws = sm;                      // 129*128 = 16512
    float* bs = Ws + 16512;              // 128
    float* dg = bs + 128;                // 32
    float* sep = dg + 32;                // 32 (pad)
    unsigned long long* vsd = (unsigned long long*)(sep + 32); // 32 rows x 130 ull
    int tid = threadIdx.x;
    int warp = tid >> 5, lane = tid & 31;
    int c4 = lane * 4;
    for (int i = tid; i < 16512; i += 256) Ws[i] = W1[i];
    if (tid < 128) bs[tid] = b1[tid];

    int iters = (N_NODES + D1_N - 1) / D1_N;
    for (int it = blockIdx.x; it < iters; it += gridDim.x) {
        int base = it * D1_N;
        __syncthreads();
        if (tid < D1_N) {
            int gn = base + tid;
            bool ok = gn < N_NODES;
            dg[tid] = ok ? g_deg[gn] + 1.0f : 1.0f;
            float s = ok ? g_se[gn] : 0.0f;
            vsd[tid * 130 + 128] = f2ull(s, s);
        }
        __syncthreads();
        for (int idx = tid; idx < D1_N * 64; idx += 256) {
            int n = idx >> 6, k = idx & 63;
            int gn = base + n;
            float xv = 0.f, sv = 0.f;
            if (gn < N_NODES) { xv = x[gn * 64 + k]; sv = g_Sx[gn * 64 + k]; }
            float a = dg[n] * xv;
            float b = sv + xv;
            vsd[n * 130 + k]      = f2ull(a, a);
            vsd[n * 130 + 64 + k] = f2ull(b, b);
        }
        __syncthreads();

        unsigned long long a0[4], a1[4];
#pragma unroll
        for (int i = 0; i < 4; i++) { a0[i] = 0ull; a1[i] = 0ull; }
        const float* wp = Ws + c4;
        const unsigned long long* v0 = vsd + (warp * 4) * 130;
        for (int k2 = 0; k2 < 64; k2++) {
            ulonglong2 wa = *(const ulonglong2*)(wp + (2 * k2) * 128);
            ulonglong2 wb = *(const ulonglong2*)(wp + (2 * k2 + 1) * 128);
#pragma unroll
            for (int i = 0; i < 4; i++) {
                ulonglong2 vv = *(const ulonglong2*)(v0 + i * 130 + 2 * k2);
                ffma2(a0[i], wa.x, vv.x); ffma2(a1[i], wa.y, vv.x);
                ffma2(a0[i], wb.x, vv.y); ffma2(a1[i], wb.y, vv.y);
            }
        }
        {   // k = 128 (edge-attr row)
            ulonglong2 wt = *(const ulonglong2*)(wp + 128 * 128);
#pragma unroll
            for (int i = 0; i < 4; i++) {
                unsigned long long vt = v0[i * 130 + 128];
                ffma2(a0[i], wt.x, vt); ffma2(a1[i], wt.y, vt);
            }
        }
#pragma unroll
        for (int i = 0; i < 4; i++) {
            int ln = warp * 4 + i;
            int gn = base + ln;
            if (gn < N_NODES) {
                float d = dg[ln];
                float2 lo = ull2f2(a0[i]), hi = ull2f2(a1[i]);
                float4 r;
                r.x = fmaxf(fmaf(d, bs[c4 + 0], lo.x), 0.f);
                r.y = fmaxf(fmaf(d, bs[c4 + 1], lo.y), 0.f);
                r.z = fmaxf(fmaf(d, bs[c4 + 2], hi.x), 0.f);
                r.w = fmaxf(fmaf(d, bs[c4 + 3], hi.y), 0.f);
                *(float4*)&g_h[gn * 128 + c4] = r;
            }
        }
    }
}

// ==================== dense layer 2 (+ fused relu & log_softmax, unchanged) ==
#define D2_N 64
__global__ __launch_bounds__(256) void dense2_kernel(
    const float* __restrict__ W2, const float* __restrict__ b2,
    float* __restrict__ out) {
    extern __shared__ float sm[];
    float* Ws = sm;                      // 257*64 = 16448
    float* bs = Ws + 16448;              // 64
    float* dg = bs + 64;                 // 64
    unsigned long long* vsd = (unsigned long long*)(dg + 64); // 64 rows x 258 ull
    int tid = threadIdx.x;
    int warp = tid >> 5, lane = tid & 31;
    int j2 = lane * 2;
    for (int i = tid; i < 16448; i += 256) Ws[i] = W2[i];
    if (tid < 64) bs[tid] = b2[tid];

    int iters = (N_NODES + D2_N - 1) / D2_N;
    for (int it = blockIdx.x; it < iters; it += gridDim.x) {
        int base = it * D2_N;
        __syncthreads();
        if (tid < D2_N) {
            int gn = base + tid;
            bool ok = gn < N_NODES;
            dg[tid] = ok ? g_deg[gn] + 1.0f : 1.0f;
            float s = ok ? g_se[gn] : 0.0f;
            vsd[tid * 258 + 256] = f2ull(s, s);
        }
        __syncthreads();
        for (int idx = tid; idx < D2_N * 128; idx += 256) {
            int n = idx >> 7, k = idx & 127;
            int gn = base + n;
            float hv = 0.f, sv = 0.f;
            if (gn < N_NODES) { hv = g_h[gn * 128 + k]; sv = g_S2[gn * 128 + k]; }
            float a = dg[n] * hv;
            float b = sv + hv;
            vsd[n * 258 + k]       = f2ull(a, a);
            vsd[n * 258 + 128 + k] = f2ull(b, b);
        }
        __syncthreads();

        unsigned long long acc[8];
#pragma unroll
        for (int i = 0; i < 8; i++) acc[i] = 0ull;
        const float* wp = Ws + j2;
        const unsigned long long* v0 = vsd + (warp * 8) * 258;
        for (int k4 = 0; k4 < 64; k4++) {
            int k = k4 * 4;
            unsigned long long w0 = *(const unsigned long long*)(wp + (k + 0) * 64);
            unsigned long long w1 = *(const unsigned long long*)(wp + (k + 1) * 64);
            unsigned long long w2 = *(const unsigned long long*)(wp + (k + 2) * 64);
            unsigned long long w3 = *(const unsigned long long*)(wp + (k + 3) * 64);
#pragma unroll
            for (int i = 0; i < 8; i++) {
                ulonglong2 va = *(const ulonglong2*)(v0 + i * 258 + k);
                ulonglong2 vb = *(const ulonglong2*)(v0 + i * 258 + k + 2);
                ffma2(acc[i], w0, va.x);
                ffma2(acc[i], w1, va.y);
                ffma2(acc[i], w2, vb.x);
                ffma2(acc[i], w3, vb.y);
            }
        }
        {   // k = 256 (edge-attr row)
            unsigned long long wt = *(const unsigned long long*)(wp + 256 * 64);
#pragma unroll
            for (int i = 0; i < 8; i++) ffma2(acc[i], wt, v0[i * 258 + 256]);
        }

        float bx = bs[j2], by = bs[j2 + 1];
#pragma unroll
        for (int i = 0; i < 8; i++) {
            int ln = warp * 8 + i;
            int gn = base + ln;
            float d = dg[ln];
            float2 a = ull2f2(acc[i]);
            float rx = fmaxf(fmaf(d, bx, a.x), 0.f);
            float ry = fmaxf(fmaf(d, by, a.y), 0.f);
            float m = fmaxf(rx, ry);
#pragma unroll
            for (int o = 16; o; o >>= 1) m = fmaxf(m, __shfl_xor_sync(0xffffffffu, m, o));
            float s = __expf(rx - m) + __expf(ry - m);
#pragma unroll
            for (int o = 16; o; o >>= 1) s += __shfl_xor_sync(0xffffffffu, s, o);
            float ls = __logf(s) + m;
            if (gn < N_NODES) {
                float2 r = make_float2(rx - ls, ry - ls);
                *(float2*)&out[gn * 64 + j2] = r;
            }
        }
    }
}

// ---------------- launch ------------------------------------------------------
extern "C" void kernel_launch(void* const* d_in, const int* in_sizes, int n_in,
                              void* d_out, int out_size) {
    const float* x  = (const float*)d_in[0];
    const void*  ei = d_in[1];
    const float* ea = (const float*)d_in[2];
    const float* W1 = (const float*)d_in[3];
    const float* b1 = (const float*)d_in[4];
    const float* W2 = (const float*)d_in[5];
    const float* b2 = (const float*)d_in[6];
    float* out = (float*)d_out;

    int smem1 = (16512 + 128 + 32 + 32) * 4 + 32 * 130 * 8;   // 100,096 B
    int smem2 = (16448 + 64 + 64) * 4 + 64 * 258 * 8;         // 198,400 B
    cudaFuncSetAttribute(dense1_kernel, cudaFuncAttributeMaxDynamicSharedMemorySize, smem1);
    cudaFuncSetAttribute(dense2_kernel, cudaFuncAttributeMaxDynamicSharedMemorySize, smem2);

    zero_kernel<<<256, 256>>>();
    detect_kernel<<<1, 256>>>((const int*)ei);
    hist_kernel<<<(N_EDGES + 255) / 256, 256>>>(ei, ea);
    scan1_kernel<<<SCAN_BLOCKS, 256>>>();
    scan2_kernel<<<1, 256>>>();
    scan3_kernel<<<SCAN_BLOCKS, 256>>>();
    fill_kernel<<<(N_EDGES + 255) / 256, 256>>>(ei);
    pull1_kernel<<<(N_NODES * 16 + 255) / 256, 256>>>(x);
    dense1_kernel<<<296, 256, smem1>>>(x, W1, b1);
    pull2_kernel<<<(N_NODES * 32 + 255) / 256, 256>>>();
    dense2_kernel<<<148, 256, smem2>>>(W2, b2, out);
}